// round 2
// baseline (speedup 1.0000x reference)
#include <cuda_runtime.h>
#include <cuda_bf16.h>

// Jagged (sorted batch_indexes) -> padded dense, output-driven gather.
//
// Inputs (metadata order):
//   d_in[0] keypoints0   float32 (N,2)
//   d_in[1] keypoints1   float32 (N,2)
//   d_in[2] confidence   float32 (N,)
//   d_in[3] batch_indexes int32 (N,)   -- sorted, contiguous runs
//   d_in[4] num_batches  (scalar)
//   d_in[5] max_points   (scalar)
// Output: concat of source_points (B,L,2), target_points (B,L,2), scores (B,L)
//         => out_size = 5*B*L float32.

#define MAX_B 65536

__device__ int g_start[MAX_B];
__device__ int g_count[MAX_B];   // phase 1: exclusive end marker; phase 2: count

// (1) reset metadata.
__global__ void zero_meta_kernel() {
    int i = blockIdx.x * blockDim.x + threadIdx.x;
    if (i < MAX_B) { g_start[i] = 0; g_count[i] = 0; }
}

// (2) boundary detection on the sorted batch_indexes array.
__global__ void boundaries_kernel(const int* __restrict__ bi, int n) {
    int i = blockIdx.x * blockDim.x + threadIdx.x;
    if (i >= n) return;
    int b = bi[i];
    if (b < 0 || b >= MAX_B) return;           // mode="drop" semantics
    if (i == 0     || bi[i - 1] != b) g_start[b] = i;
    if (i == n - 1 || bi[i + 1] != b) g_count[b] = i + 1;  // exclusive end
}

// (3) count = end - start where a run was seen.
__global__ void finalize_kernel() {
    int b = blockIdx.x * blockDim.x + threadIdx.x;
    if (b < MAX_B && g_count[b] > 0) g_count[b] -= g_start[b];
}

// (4) gather: one thread per PAIR of (b,p) slots. Slots 2k,2k+1 share a batch
//     when L is even (guarded otherwise). float4 stores for keypoints; float2
//     loads (source offset may be only 8B-aligned). Grid-stride.
__global__ void gather2_kernel(const float2* __restrict__ kp0,
                               const float2* __restrict__ kp1,
                               const float*  __restrict__ conf,
                               float4* __restrict__ out_src,
                               float4* __restrict__ out_tgt,
                               float2* __restrict__ out_sc,
                               const int* __restrict__ max_points_p,
                               int npairs) {
    int L = max_points_p[0];                 // little-endian low word ok for i32/i64
    bool Leven = (L & 1) == 0;
    for (int k = blockIdx.x * blockDim.x + threadIdx.x; k < npairs;
         k += gridDim.x * blockDim.x) {
        int idx = k * 2;                     // first slot of the pair
        int b   = idx / L;
        int p   = idx - b * L;

        float4 s = make_float4(0.f, 0.f, 0.f, 0.f);
        float4 t = make_float4(0.f, 0.f, 0.f, 0.f);
        float2 c = make_float2(0.f, 0.f);

        if (Leven) {
            int cnt = g_count[b];
            int st  = g_start[b];
            if (p < cnt) {
                int j = st + p;
                float2 s0 = kp0[j], t0 = kp1[j];
                s.x = s0.x; s.y = s0.y;
                t.x = t0.x; t.y = t0.y;
                c.x = conf[j];
            }
            if (p + 1 < cnt) {
                int j = st + p + 1;
                float2 s1 = kp0[j], t1 = kp1[j];
                s.z = s1.x; s.w = s1.y;
                t.z = t1.x; t.w = t1.y;
                c.y = conf[j];
            }
        } else {
            // odd-L fallback: slots of the pair may be in different batches
            int b1 = (idx + 1) / L;
            int p1 = (idx + 1) - b1 * L;
            if (p < g_count[b]) {
                int j = g_start[b] + p;
                float2 s0 = kp0[j], t0 = kp1[j];
                s.x = s0.x; s.y = s0.y;
                t.x = t0.x; t.y = t0.y;
                c.x = conf[j];
            }
            if (p1 < g_count[b1]) {
                int j = g_start[b1] + p1;
                float2 s1 = kp0[j], t1 = kp1[j];
                s.z = s1.x; s.w = s1.y;
                t.z = t1.x; t.w = t1.y;
                c.y = conf[j];
            }
        }
        out_src[k] = s;
        out_tgt[k] = t;
        out_sc[k]  = c;
    }
}

// Scalar tail for odd total (not hit for this dataset; kept for correctness).
__global__ void gather_tail_kernel(const float2* __restrict__ kp0,
                                   const float2* __restrict__ kp1,
                                   const float*  __restrict__ conf,
                                   float2* __restrict__ out_src,
                                   float2* __restrict__ out_tgt,
                                   float*  __restrict__ out_sc,
                                   const int* __restrict__ max_points_p,
                                   int begin, int total) {
    int idx = begin + blockIdx.x * blockDim.x + threadIdx.x;
    if (idx >= total) return;
    int L = max_points_p[0];
    int b = idx / L;
    int p = idx - b * L;
    float2 s = make_float2(0.f, 0.f), t = make_float2(0.f, 0.f);
    float  c = 0.f;
    if (p < g_count[b]) {
        int j = g_start[b] + p;
        s = kp0[j]; t = kp1[j]; c = conf[j];
    }
    out_src[idx] = s; out_tgt[idx] = t; out_sc[idx] = c;
}

extern "C" void kernel_launch(void* const* d_in, const int* in_sizes, int n_in,
                              void* d_out, int out_size) {
    const float2* kp0  = (const float2*)d_in[0];
    const float2* kp1  = (const float2*)d_in[1];
    const float*  conf = (const float*)d_in[2];
    const int*    bi   = (const int*)d_in[3];
    const int*    maxp = (const int*)d_in[5];

    int n = in_sizes[2];               // N
    int total = out_size / 5;          // B * L

    float* out = (float*)d_out;
    float2* out_src = (float2*)out;                      // B*L float2
    float2* out_tgt = (float2*)(out + 2LL * total);
    float*  out_sc  = out + 4LL * total;

    zero_meta_kernel<<<MAX_B / 256, 256>>>();
    boundaries_kernel<<<(n + 255) / 256, 256>>>(bi, n);
    finalize_kernel<<<MAX_B / 256, 256>>>();

    int npairs = total / 2;
    if (npairs > 0) {
        int threads = 256;
        long long want = ((long long)npairs + threads - 1) / threads;
        int blocks = (int)(want > 8 * 148 * 8 ? 8 * 148 * 8 : want);  // cap grid
        if (blocks < 1) blocks = 1;
        gather2_kernel<<<blocks, threads>>>(kp0, kp1, conf,
                                            (float4*)out_src, (float4*)out_tgt,
                                            (float2*)out_sc, maxp, npairs);
    }
    int done = npairs * 2;
    if (done < total) {
        int rem = total - done;
        gather_tail_kernel<<<(rem + 255) / 256, 256>>>(kp0, kp1, conf,
                                                       out_src, out_tgt, out_sc,
                                                       maxp, done, total);
    }
}

// round 13
// speedup vs baseline: 1.3290x; 1.3290x over previous
#include <cuda_runtime.h>
#include <cuda_bf16.h>

// Jagged (sorted batch_indexes) -> padded dense, output-driven gather.
//
// Inputs (metadata order):
//   d_in[0] keypoints0    float32 (N,2)
//   d_in[1] keypoints1    float32 (N,2)
//   d_in[2] confidence    float32 (N,)
//   d_in[3] batch_indexes int32 (N,)   -- sorted, contiguous runs
//   d_in[4] num_batches   (scalar)
//   d_in[5] max_points    (scalar)
// Output: concat of source_points (B,L,2), target_points (B,L,2), scores (B,L)
//         => out_size = 5*B*L float32.
//
// Metadata via per-batch binary search (no full scan, no zero-fill needed:
// every entry is recomputed each launch, so the graph replays correctly).

#define MAX_B 65536

__device__ int g_start[MAX_B + 1];   // g_start[b] = lower_bound(bi, b); count = diff

// (1) one thread per b in [0, MAX_B]: lower_bound of b in the sorted array.
__global__ void binsearch_kernel(const int* __restrict__ bi, int n) {
    int b = blockIdx.x * blockDim.x + threadIdx.x;
    if (b > MAX_B) return;
    int lo = 0, hi = n;              // first index with bi[i] >= b
    while (lo < hi) {
        int mid = (lo + hi) >> 1;
        if (bi[mid] < b) lo = mid + 1;
        else             hi = mid;
    }
    g_start[b] = lo;
}

// (2) gather: one thread per PAIR of (b,p) slots. Slots 2k,2k+1 share a batch
//     when L is even (guarded otherwise). float4 stores for keypoints; float2
//     loads (source offset may be only 8B-aligned). Grid-stride.
__global__ void gather2_kernel(const float2* __restrict__ kp0,
                               const float2* __restrict__ kp1,
                               const float*  __restrict__ conf,
                               float4* __restrict__ out_src,
                               float4* __restrict__ out_tgt,
                               float2* __restrict__ out_sc,
                               const int* __restrict__ max_points_p,
                               int npairs) {
    int L = max_points_p[0];                 // little-endian low word ok for i32/i64
    bool Leven = (L & 1) == 0;
    for (int k = blockIdx.x * blockDim.x + threadIdx.x; k < npairs;
         k += gridDim.x * blockDim.x) {
        int idx = k * 2;                     // first slot of the pair
        int b   = idx / L;
        int p   = idx - b * L;

        float4 s = make_float4(0.f, 0.f, 0.f, 0.f);
        float4 t = make_float4(0.f, 0.f, 0.f, 0.f);
        float2 c = make_float2(0.f, 0.f);

        if (Leven) {
            int st  = g_start[b];
            int cnt = g_start[b + 1] - st;
            if (p < cnt) {
                int j = st + p;
                float2 s0 = kp0[j], t0 = kp1[j];
                s.x = s0.x; s.y = s0.y;
                t.x = t0.x; t.y = t0.y;
                c.x = conf[j];
            }
            if (p + 1 < cnt) {
                int j = st + p + 1;
                float2 s1 = kp0[j], t1 = kp1[j];
                s.z = s1.x; s.w = s1.y;
                t.z = t1.x; t.w = t1.y;
                c.y = conf[j];
            }
        } else {
            // odd-L fallback: the two slots may belong to different batches
            int b1 = (idx + 1) / L;
            int p1 = (idx + 1) - b1 * L;
            int st0 = g_start[b],  cnt0 = g_start[b  + 1] - st0;
            int st1 = g_start[b1], cnt1 = g_start[b1 + 1] - st1;
            if (p < cnt0) {
                int j = st0 + p;
                float2 s0 = kp0[j], t0 = kp1[j];
                s.x = s0.x; s.y = s0.y;
                t.x = t0.x; t.y = t0.y;
                c.x = conf[j];
            }
            if (p1 < cnt1) {
                int j = st1 + p1;
                float2 s1 = kp0[j], t1 = kp1[j];
                s.z = s1.x; s.w = s1.y;
                t.z = t1.x; t.w = t1.y;
                c.y = conf[j];
            }
        }
        out_src[k] = s;
        out_tgt[k] = t;
        out_sc[k]  = c;
    }
}

// Scalar tail for odd total (not hit for this dataset; kept for correctness).
__global__ void gather_tail_kernel(const float2* __restrict__ kp0,
                                   const float2* __restrict__ kp1,
                                   const float*  __restrict__ conf,
                                   float2* __restrict__ out_src,
                                   float2* __restrict__ out_tgt,
                                   float*  __restrict__ out_sc,
                                   const int* __restrict__ max_points_p,
                                   int begin, int total) {
    int idx = begin + blockIdx.x * blockDim.x + threadIdx.x;
    if (idx >= total) return;
    int L = max_points_p[0];
    int b = idx / L;
    int p = idx - b * L;
    int st  = g_start[b];
    int cnt = g_start[b + 1] - st;
    float2 s = make_float2(0.f, 0.f), t = make_float2(0.f, 0.f);
    float  c = 0.f;
    if (p < cnt) {
        int j = st + p;
        s = kp0[j]; t = kp1[j]; c = conf[j];
    }
    out_src[idx] = s; out_tgt[idx] = t; out_sc[idx] = c;
}

extern "C" void kernel_launch(void* const* d_in, const int* in_sizes, int n_in,
                              void* d_out, int out_size) {
    const float2* kp0  = (const float2*)d_in[0];
    const float2* kp1  = (const float2*)d_in[1];
    const float*  conf = (const float*)d_in[2];
    const int*    bi   = (const int*)d_in[3];
    const int*    maxp = (const int*)d_in[5];

    int n = in_sizes[2];               // N
    int total = out_size / 5;          // B * L

    float* out = (float*)d_out;
    float2* out_src = (float2*)out;                      // B*L float2
    float2* out_tgt = (float2*)(out + 2LL * total);
    float*  out_sc  = out + 4LL * total;

    binsearch_kernel<<<(MAX_B + 1 + 255) / 256, 256>>>(bi, n);

    int npairs = total / 2;
    if (npairs > 0) {
        int threads = 256;
        long long want = ((long long)npairs + threads - 1) / threads;
        int blocks = (int)(want > 8 * 148 * 8 ? 8 * 148 * 8 : want);  // cap grid
        if (blocks < 1) blocks = 1;
        gather2_kernel<<<blocks, threads>>>(kp0, kp1, conf,
                                            (float4*)out_src, (float4*)out_tgt,
                                            (float2*)out_sc, maxp, npairs);
    }
    int done = npairs * 2;
    if (done < total) {
        int rem = total - done;
        gather_tail_kernel<<<(rem + 255) / 256, 256>>>(kp0, kp1, conf,
                                                       out_src, out_tgt, out_sc,
                                                       maxp, done, total);
    }
}